// round 14
// baseline (speedup 1.0000x reference)
#include <cuda_runtime.h>
#include <cuda_bf16.h>
#include <stdint.h>
#include <math.h>

#define N_NODES 50000
#define F_IN    1433
#define KP1     1440          // F_IN padded to 32 multiple
#define KSPLIT  736           // GEMM1 K-halves: 736 + 704 (both BK multiples)
#define HDIM    256
#define NCLS    7
#define EDGES_MAX 800000
#define NSCAN_BLK 49          // ceil(50000/1024)

// ---------------- scratch (static device arrays; no cudaMalloc) ----------------
__device__ int   g_cnt[N_NODES];
__device__ int   g_off[N_NODES + 1];
__device__ int   g_cur[N_NODES];
__device__ int   g_bsum[64];
__device__ int   g_bsumx[64];
__device__ float g_dinv[N_NODES];
__device__ int2  g_csr[EDGES_MAX];

__device__ __align__(16) __nv_bfloat16 g_xh[(size_t)N_NODES * KP1];
__device__ __align__(16) __nv_bfloat16 g_xl[(size_t)N_NODES * KP1];
__device__ __align__(16) __nv_bfloat16 g_w1h[KP1 * HDIM];
__device__ __align__(16) __nv_bfloat16 g_w1l[KP1 * HDIM];
__device__ __align__(16) __nv_bfloat16 g_w2h[HDIM * HDIM];
__device__ __align__(16) __nv_bfloat16 g_w2l[HDIM * HDIM];
__device__ __align__(16) float g_h[(size_t)N_NODES * HDIM];
__device__ __align__(16) __nv_bfloat16 g_a1h[(size_t)N_NODES * HDIM];
__device__ __align__(16) __nv_bfloat16 g_a1l[(size_t)N_NODES * HDIM];
__device__ __align__(16) __nv_bfloat16 g_a2h[(size_t)N_NODES * HDIM];
__device__ __align__(16) __nv_bfloat16 g_a2l[(size_t)N_NODES * HDIM];
__device__ __align__(16) float g_h3[N_NODES * 8];
__device__ __align__(16) float g_a3[N_NODES * 8];

// ---------------- CSR build + parallel scan ----------------
__global__ void k_zero_cnt() {
    int i = blockIdx.x * blockDim.x + threadIdx.x;
    if (i < N_NODES) g_cnt[i] = 0;
}
__global__ void k_cnt_edges(const int* __restrict__ dst, int E) {
    int e = blockIdx.x * blockDim.x + threadIdx.x;
    if (e < E) atomicAdd(&g_cnt[dst[e]], 1);
}
__global__ void k_dinv() {
    int i = blockIdx.x * blockDim.x + threadIdx.x;
    if (i < N_NODES) g_dinv[i] = rsqrtf(1.0f + (float)g_cnt[i]);
}
__global__ __launch_bounds__(1024) void k_scan1() {
    __shared__ int wsum[32];
    int tid = threadIdx.x, lane = tid & 31, w = tid >> 5;
    int i = blockIdx.x * 1024 + tid;
    int v = (i < N_NODES) ? g_cnt[i] : 0;
    int x = v;
#pragma unroll
    for (int o = 1; o < 32; o <<= 1) {
        int y = __shfl_up_sync(~0u, x, o);
        if (lane >= o) x += y;
    }
    if (lane == 31) wsum[w] = x;
    __syncthreads();
    if (w == 0) {
        int s = wsum[lane];
#pragma unroll
        for (int o = 1; o < 32; o <<= 1) {
            int y = __shfl_up_sync(~0u, s, o);
            if (lane >= o) s += y;
        }
        wsum[lane] = s;
    }
    __syncthreads();
    int excl = x - v + (w ? wsum[w - 1] : 0);
    if (i < N_NODES) g_off[i] = excl;
    if (tid == 0) g_bsum[blockIdx.x] = wsum[31];
}
__global__ void k_scan2(int nb) {
    __shared__ int ws[2];
    int t = threadIdx.x, lane = t & 31, w = t >> 5;
    int v = (t < nb) ? g_bsum[t] : 0;
    int x = v;
#pragma unroll
    for (int o = 1; o < 32; o <<= 1) {
        int y = __shfl_up_sync(~0u, x, o);
        if (lane >= o) x += y;
    }
    if (lane == 31) ws[w] = x;
    __syncthreads();
    int incl = x + (w == 1 ? ws[0] : 0);
    if (t < 64) g_bsumx[t] = incl - v;
    if (t == 63) g_off[N_NODES] = ws[0] + ws[1];
}
__global__ __launch_bounds__(1024) void k_scan3() {
    int i = blockIdx.x * 1024 + threadIdx.x;
    if (i < N_NODES) {
        int o = g_off[i] + g_bsumx[i >> 10];
        g_off[i] = o;
        g_cur[i] = o;
    }
}
__global__ void k_csr_fill(const int* __restrict__ src, const int* __restrict__ dst, int E) {
    int e = blockIdx.x * blockDim.x + threadIdx.x;
    if (e >= E) return;
    int r = src[e], d = dst[e];
    int pos = atomicAdd(&g_cur[d], 1);
    g_csr[pos] = make_int2(r, __float_as_int(g_dinv[r] * g_dinv[d]));
}

// ---------------- operand prep: fp32 -> bf16 hi/lo ----------------
__device__ __forceinline__ void split4(const float v[4], unsigned h2[2], unsigned l2[2]) {
#pragma unroll
    for (int p = 0; p < 2; p++) {
        __nv_bfloat162 hb = __floats2bfloat162_rn(v[2 * p], v[2 * p + 1]);
        float2 hf = __bfloat1622float2(hb);
        __nv_bfloat162 lb = __floats2bfloat162_rn(v[2 * p] - hf.x, v[2 * p + 1] - hf.y);
        h2[p] = *reinterpret_cast<unsigned*>(&hb);
        l2[p] = *reinterpret_cast<unsigned*>(&lb);
    }
}
// split a k-range [kbeg, kend) of x (kbeg/kend multiples of 4)
__global__ void k_split_x(const float* __restrict__ x, int kbeg, int kend) {
    const int nc4 = (kend - kbeg) >> 2;
    long t = (long)blockIdx.x * blockDim.x + threadIdx.x;
    if (t >= (long)N_NODES * nc4) return;
    int row = (int)(t / nc4);
    int k = kbeg + (int)(t % nc4) * 4;
    float v[4];
#pragma unroll
    for (int j = 0; j < 4; j++)
        v[j] = (k + j < F_IN) ? __ldg(&x[(long)row * F_IN + k + j]) : 0.0f;
    unsigned h2[2], l2[2];
    split4(v, h2, l2);
    *reinterpret_cast<uint2*>(&g_xh[(long)row * KP1 + k]) = make_uint2(h2[0], h2[1]);
    *reinterpret_cast<uint2*>(&g_xl[(long)row * KP1 + k]) = make_uint2(l2[0], l2[1]);
}
__global__ void k_split_w(const float* __restrict__ W, __nv_bfloat16* __restrict__ Wh,
                          __nv_bfloat16* __restrict__ Wl, int K, int Kp) {
    int t = blockIdx.x * blockDim.x + threadIdx.x;
    if (t >= Kp * (HDIM / 4)) return;
    int k = t / (HDIM / 4);
    int n4 = t % (HDIM / 4);
    float v[4] = {0.f, 0.f, 0.f, 0.f};
    if (k < K) {
        float4 f = __ldg(reinterpret_cast<const float4*>(&W[(long)k * HDIM + n4 * 4]));
        v[0] = f.x; v[1] = f.y; v[2] = f.z; v[3] = f.w;
    }
    unsigned h2[2], l2[2];
    split4(v, h2, l2);
    *reinterpret_cast<uint2*>(&Wh[(long)k * HDIM + n4 * 4]) = make_uint2(h2[0], h2[1]);
    *reinterpret_cast<uint2*>(&Wl[(long)k * HDIM + n4 * 4]) = make_uint2(l2[0], l2[1]);
}

// =====================================================================
// bf16 split-precision tensor-core GEMM (R11-proven inner loop).
// K-windowed: processes k in [koff, koff+Kcnt) of a matrix with row
// stride Kst; accum!=0 adds into existing C.
// =====================================================================
#define BM 128
#define BN 64
#define BK 32

__device__ __forceinline__ int swzA(int m, int c) {
    return (m >> 1) * 8 + ((((m & 1) * 4) + c) ^ ((m >> 1) & 7));
}
__device__ __forceinline__ int swzB(int k, int c) {
    return k * 8 + (c ^ (k & 7));
}
__device__ __forceinline__ void cp16(uint4* smem, const uint4* g, bool valid) {
    unsigned s = (unsigned)__cvta_generic_to_shared(smem);
    int sz = valid ? 16 : 0;
    asm volatile("cp.async.ca.shared.global [%0], [%1], 16, %2;"
                 :: "r"(s), "l"(g), "r"(sz));
}
__device__ __forceinline__ void cp_commit() { asm volatile("cp.async.commit_group;"); }
__device__ __forceinline__ void cp_wait_all() { asm volatile("cp.async.wait_group 0;"); }

__device__ __forceinline__ void ldsm_x4(unsigned r[4], const void* p) {
    unsigned a = (unsigned)__cvta_generic_to_shared(p);
    asm volatile("ldmatrix.sync.aligned.m8n8.x4.shared.b16 {%0,%1,%2,%3}, [%4];"
                 : "=r"(r[0]), "=r"(r[1]), "=r"(r[2]), "=r"(r[3]) : "r"(a));
}
__device__ __forceinline__ void ldsm_x4_t(unsigned r[4], const void* p) {
    unsigned a = (unsigned)__cvta_generic_to_shared(p);
    asm volatile("ldmatrix.sync.aligned.m8n8.x4.trans.shared.b16 {%0,%1,%2,%3}, [%4];"
                 : "=r"(r[0]), "=r"(r[1]), "=r"(r[2]), "=r"(r[3]) : "r"(a));
}
__device__ __forceinline__ void mma_bf16(float c[4], const unsigned a[4],
                                         unsigned b0, unsigned b1) {
    asm volatile(
        "mma.sync.aligned.m16n8k16.row.col.f32.bf16.bf16.f32 "
        "{%0,%1,%2,%3}, {%4,%5,%6,%7}, {%8,%9}, {%0,%1,%2,%3};"
        : "+f"(c[0]), "+f"(c[1]), "+f"(c[2]), "+f"(c[3])
        : "r"(a[0]), "r"(a[1]), "r"(a[2]), "r"(a[3]), "r"(b0), "r"(b1));
}

__global__ __launch_bounds__(256, 2)
void k_gemm_bf3(const __nv_bfloat16* __restrict__ Ah, const __nv_bfloat16* __restrict__ Al,
                const __nv_bfloat16* __restrict__ Bh_, const __nv_bfloat16* __restrict__ Bl_,
                float* __restrict__ C, int M, int Kst, int koff, int Kcnt, int accum) {
    __shared__ uint4 sAh[2][512], sAl[2][512], sBh[2][256], sBl[2][256];

    const int tid = threadIdx.x, warp = tid >> 5, lane = tid & 31;
    const int m0 = blockIdx.y * BM, n0 = blockIdx.x * BN;
    const int wm = (warp >> 1) * 32, wn = (warp & 1) * 32;
    const int g = lane >> 2, tg = lane & 3;

    const uint4* Ah4 = reinterpret_cast<const uint4*>(Ah);
    const uint4* Al4 = reinterpret_cast<const uint4*>(Al);
    const uint4* Bh4 = reinterpret_cast<const uint4*>(Bh_);
    const uint4* Bl4 = reinterpret_cast<const uint4*>(Bl_);
    const int Kst4 = Kst >> 3;
    const int ko4 = koff >> 3;
    const int n08 = n0 >> 3;

    const int a_m = tid >> 2, a_c = tid & 3;
    const int b_k = tid >> 3, b_c = tid & 7;
    const int gm0 = m0 + a_m, gm1 = gm0 + 64;
    const bool v0 = gm0 < M, v1 = gm1 < M;
    const long aRow0 = (long)(v0 ? gm0 : 0) * Kst4 + ko4;
    const long aRow1 = (long)(v1 ? gm1 : 0) * Kst4 + ko4;
    const int sA0 = swzA(a_m, a_c), sA1 = swzA(a_m + 64, a_c);
    const int sB = swzB(b_k, b_c);

    auto issue = [&](int t, int buf) {
        long ac  = aRow0 + t * 4 + a_c;
        long ac1 = aRow1 + t * 4 + a_c;
        cp16(&sAh[buf][sA0], &Ah4[ac],  v0);
        cp16(&sAl[buf][sA0], &Al4[ac],  v0);
        cp16(&sAh[buf][sA1], &Ah4[ac1], v1);
        cp16(&sAl[buf][sA1], &Al4[ac1], v1);
        long bc = (long)(koff + t * 32 + b_k) * (HDIM / 8) + n08 + b_c;
        cp16(&sBh[buf][sB], &Bh4[bc], true);
        cp16(&sBl[buf][sB], &Bl4[bc], true);
        cp_commit();
    };

    float acc[2][4][4];
#pragma unroll
    for (int i = 0; i < 2; i++)
#pragma unroll
        for (int j = 0; j < 4; j++)
#pragma unroll
            for (int r = 0; r < 4; r++) acc[i][j][r] = 0.0f;

    const int T = Kcnt / BK;
    issue(0, 0);
    for (int t = 0; t < T; t++) {
        cp_wait_all();
        __syncthreads();
        const int cur = t & 1;
        if (t + 1 < T) issue(t + 1, cur ^ 1);

#pragma unroll
        for (int ks = 0; ks < 2; ks++) {
            unsigned ah[2][4], al[2][4], bh[2][4], bl[2][4];
#pragma unroll
            for (int mi = 0; mi < 2; mi++) {
                int row = wm + mi * 16 + (lane & 15);
                int c = ks * 2 + (lane >> 4);
                ldsm_x4(ah[mi], &sAh[cur][swzA(row, c)]);
                ldsm_x4(al[mi], &sAl[cur][swzA(row, c)]);
            }
#pragma unroll
            for (int njp = 0; njp < 2; njp++) {
                int krow = ks * 16 + ((lane >> 3) & 1) * 8 + (lane & 7);
                int c = (wn >> 3) + 2 * njp + (lane >> 4);
                ldsm_x4_t(bh[njp], &sBh[cur][swzB(krow, c)]);
                ldsm_x4_t(bl[njp], &sBl[cur][swzB(krow, c)]);
            }
#pragma unroll
            for (int mi = 0; mi < 2; mi++)
#pragma unroll
                for (int njp = 0; njp < 2; njp++)
#pragma unroll
                    for (int sub = 0; sub < 2; sub++) {
                        int nj = njp * 2 + sub;
                        mma_bf16(acc[mi][nj], ah[mi], bh[njp][2*sub], bh[njp][2*sub+1]);
                        mma_bf16(acc[mi][nj], ah[mi], bl[njp][2*sub], bl[njp][2*sub+1]);
                        mma_bf16(acc[mi][nj], al[mi], bh[njp][2*sub], bh[njp][2*sub+1]);
                    }
        }
        __syncthreads();
    }

#pragma unroll
    for (int mi = 0; mi < 2; mi++) {
        int row0 = m0 + wm + mi * 16 + g;
        int row1 = row0 + 8;
#pragma unroll
        for (int nj = 0; nj < 4; nj++) {
            int col = n0 + wn + nj * 8 + tg * 2;
            if (row0 < M) {
                float2* p = reinterpret_cast<float2*>(&C[(long)row0 * HDIM + col]);
                float2 v = make_float2(acc[mi][nj][0], acc[mi][nj][1]);
                if (accum) { float2 o = *p; v.x += o.x; v.y += o.y; }
                *p = v;
            }
            if (row1 < M) {
                float2* p = reinterpret_cast<float2*>(&C[(long)row1 * HDIM + col]);
                float2 v = make_float2(acc[mi][nj][2], acc[mi][nj][3]);
                if (accum) { float2 o = *p; v.x += o.x; v.y += o.y; }
                *p = v;
            }
        }
    }
}

// ---------------- CSR aggregation (gather, no atomics) ----------------
__global__ __launch_bounds__(128)
void k_agg(const float* __restrict__ h, const float* __restrict__ bias,
           __nv_bfloat16* __restrict__ oh, __nv_bfloat16* __restrict__ ol) {
    int node = blockIdx.x * 2 + (threadIdx.x >> 6);
    int f4 = threadIdx.x & 63;
    if (node >= N_NODES) return;
    float d = g_dinv[node];
    float s = d * d;
    float4 acc = __ldg(reinterpret_cast<const float4*>(bias) + f4);
    float4 hv = __ldg(reinterpret_cast<const float4*>(h + (long)node * HDIM) + f4);
    acc.x += s * hv.x; acc.y += s * hv.y; acc.z += s * hv.z; acc.w += s * hv.w;
    int st = g_off[node], en = g_off[node + 1];
    for (int i = st; i < en; i++) {
        int2 ent = __ldg(&g_csr[i]);
        float nrm = __int_as_float(ent.y);
        float4 v = __ldg(reinterpret_cast<const float4*>(h + (long)ent.x * HDIM) + f4);
        acc.x += nrm * v.x; acc.y += nrm * v.y; acc.z += nrm * v.z; acc.w += nrm * v.w;
    }
    float v[4] = { fmaxf(acc.x, 0.f), fmaxf(acc.y, 0.f), fmaxf(acc.z, 0.f), fmaxf(acc.w, 0.f) };
    unsigned h2[2], l2[2];
    split4(v, h2, l2);
    *reinterpret_cast<uint2*>(&oh[(long)node * HDIM + f4 * 4]) = make_uint2(h2[0], h2[1]);
    *reinterpret_cast<uint2*>(&ol[(long)node * HDIM + f4 * 4]) = make_uint2(l2[0], l2[1]);
}

// ---------------- layer 3 ----------------
__global__ __launch_bounds__(256)
void k_gemm3(const __nv_bfloat16* __restrict__ Ahd, const __nv_bfloat16* __restrict__ Ald,
             const float* __restrict__ W) {
    __shared__ float Ws[HDIM * NCLS];
    int tid = threadIdx.x;
    for (int i = tid; i < HDIM * NCLS; i += 256) Ws[i] = W[i];
    __syncthreads();
    int warp = tid >> 5, lane = tid & 31;
    int row = blockIdx.x * 8 + warp;
    if (row >= N_NODES) return;
    uint4 uh = __ldg(reinterpret_cast<const uint4*>(Ahd + (long)row * HDIM) + lane);
    uint4 ul = __ldg(reinterpret_cast<const uint4*>(Ald + (long)row * HDIM) + lane);
    float v[8];
    const unsigned* hu = reinterpret_cast<const unsigned*>(&uh);
    const unsigned* lu = reinterpret_cast<const unsigned*>(&ul);
#pragma unroll
    for (int p = 0; p < 4; p++) {
        float2 hf = __bfloat1622float2(*reinterpret_cast<const __nv_bfloat162*>(&hu[p]));
        float2 lf = __bfloat1622float2(*reinterpret_cast<const __nv_bfloat162*>(&lu[p]));
        v[2*p] = hf.x + lf.x; v[2*p+1] = hf.y + lf.y;
    }
    int k0 = lane * 8;
    float acc[NCLS];
#pragma unroll
    for (int c = 0; c < NCLS; c++) acc[c] = 0.0f;
#pragma unroll
    for (int j = 0; j < 8; j++)
#pragma unroll
        for (int c = 0; c < NCLS; c++)
            acc[c] = fmaf(v[j], Ws[(k0 + j) * NCLS + c], acc[c]);
#pragma unroll
    for (int c = 0; c < NCLS; c++)
#pragma unroll
        for (int off = 16; off; off >>= 1)
            acc[c] += __shfl_down_sync(0xffffffffu, acc[c], off);
    if (lane == 0) {
#pragma unroll
        for (int c = 0; c < NCLS; c++) g_h3[row * 8 + c] = acc[c];
        g_h3[row * 8 + 7] = 0.0f;
    }
}
__global__ __launch_bounds__(256)
void k_agg3(const float* __restrict__ b3) {
    int node = blockIdx.x * 32 + (threadIdx.x >> 3);
    int c = threadIdx.x & 7;
    if (node >= N_NODES || c >= NCLS) return;
    float d = g_dinv[node];
    float acc = b3[c] + d * d * g_h3[node * 8 + c];
    int st = g_off[node], en = g_off[node + 1];
    for (int i = st; i < en; i++) {
        int2 ent = __ldg(&g_csr[i]);
        acc += __int_as_float(ent.y) * g_h3[ent.x * 8 + c];
    }
    g_a3[node * 8 + c] = acc;
}
__global__ void k_log_softmax(float* __restrict__ out) {
    int i = blockIdx.x * blockDim.x + threadIdx.x;
    if (i >= N_NODES) return;
    float v[NCLS];
    float m = -INFINITY;
#pragma unroll
    for (int c = 0; c < NCLS; c++) { v[c] = g_a3[i * 8 + c]; m = fmaxf(m, v[c]); }
    float s = 0.0f;
#pragma unroll
    for (int c = 0; c < NCLS; c++) s += __expf(v[c] - m);
    float lse = m + __logf(s);
#pragma unroll
    for (int c = 0; c < NCLS; c++) out[i * NCLS + c] = v[c] - lse;
}

// ---------------- launch (two-stream fork/join inside capture) ----------------
extern "C" void kernel_launch(void* const* d_in, const int* in_sizes, int n_in,
                              void* d_out, int out_size) {
    const float* x  = (const float*)d_in[0];
    const int*   ei = (const int*)d_in[1];
    const float* W1 = (const float*)d_in[2];
    const float* b1 = (const float*)d_in[3];
    const float* W2 = (const float*)d_in[4];
    const float* b2 = (const float*)d_in[5];
    const float* W3 = (const float*)d_in[6];
    const float* b3 = (const float*)d_in[7];
    float* out = (float*)d_out;

    const int E = in_sizes[1] / 2;
    const int* src = ei;
    const int* dst = ei + E;

    __nv_bfloat16 *xh, *xl, *w1h, *w1l, *w2h, *w2l, *a1h, *a1l, *a2h, *a2l;
    float* gh;
    cudaGetSymbolAddress((void**)&xh, g_xh);   cudaGetSymbolAddress((void**)&xl, g_xl);
    cudaGetSymbolAddress((void**)&w1h, g_w1h); cudaGetSymbolAddress((void**)&w1l, g_w1l);
    cudaGetSymbolAddress((void**)&w2h, g_w2h); cudaGetSymbolAddress((void**)&w2l, g_w2l);
    cudaGetSymbolAddress((void**)&a1h, g_a1h); cudaGetSymbolAddress((void**)&a1l, g_a1l);
    cudaGetSymbolAddress((void**)&a2h, g_a2h); cudaGetSymbolAddress((void**)&a2l, g_a2l);
    cudaGetSymbolAddress((void**)&gh, g_h);

    // one-time host resources (created on the uncaptured correctness call)
    static cudaStream_t s2 = nullptr;
    static cudaEvent_t evFork = nullptr, evCSR = nullptr, evXb = nullptr;
    if (!s2) {
        cudaStreamCreateWithFlags(&s2, cudaStreamNonBlocking);
        cudaEventCreateWithFlags(&evFork, cudaEventDisableTiming);
        cudaEventCreateWithFlags(&evCSR, cudaEventDisableTiming);
        cudaEventCreateWithFlags(&evXb, cudaEventDisableTiming);
    }

    // ---- fork
    cudaEventRecord(evFork, 0);
    cudaStreamWaitEvent(s2, evFork, 0);

    // side stream: CSR chain, then W2 split + second X half
    k_zero_cnt<<<(N_NODES + 255) / 256, 256, 0, s2>>>();
    k_cnt_edges<<<(E + 255) / 256, 256, 0, s2>>>(dst, E);
    k_dinv<<<(N_NODES + 255) / 256, 256, 0, s2>>>();
    k_scan1<<<NSCAN_BLK, 1024, 0, s2>>>();
    k_scan2<<<1, 64, 0, s2>>>(NSCAN_BLK);
    k_scan3<<<NSCAN_BLK, 1024, 0, s2>>>();
    k_csr_fill<<<(E + 255) / 256, 256, 0, s2>>>(src, dst, E);
    cudaEventRecord(evCSR, s2);
    k_split_w<<<(HDIM * 64 + 255) / 256, 256, 0, s2>>>(W2, w2h, w2l, HDIM, HDIM);
    {
        long tb = (long)N_NODES * ((KP1 - KSPLIT) / 4);
        k_split_x<<<(unsigned)((tb + 255) / 256), 256, 0, s2>>>(x, KSPLIT, KP1);
    }
    cudaEventRecord(evXb, s2);

    // main stream: W1 split + first X half + GEMM1a
    k_split_w<<<(KP1 * 64 + 255) / 256, 256>>>(W1, w1h, w1l, F_IN, KP1);
    {
        long ta = (long)N_NODES * (KSPLIT / 4);
        k_split_x<<<(unsigned)((ta + 255) / 256), 256>>>(x, 0, KSPLIT);
    }
    dim3 gemm_grid(HDIM / BN, (N_NODES + BM - 1) / BM);
    k_gemm_bf3<<<gemm_grid, 256>>>(xh, xl, w1h, w1l, gh, N_NODES, KP1, 0, KSPLIT, 0);

    // second K half (accumulates); needs side stream's split_x half
    cudaStreamWaitEvent(0, evXb, 0);
    k_gemm_bf3<<<gemm_grid, 256>>>(xh, xl, w1h, w1l, gh, N_NODES, KP1, KSPLIT, KP1 - KSPLIT, 1);

    // ---- join: agg needs g_dinv / g_off / g_csr
    cudaStreamWaitEvent(0, evCSR, 0);
    k_agg<<<(N_NODES + 1) / 2, 128>>>(gh, b1, a1h, a1l);

    // layer 2 (w2 ready: evXb wait above ordered after split_w on s2)
    k_gemm_bf3<<<gemm_grid, 256>>>(a1h, a1l, w2h, w2l, gh, N_NODES, HDIM, 0, HDIM, 0);
    k_agg<<<(N_NODES + 1) / 2, 128>>>(gh, b2, a2h, a2l);

    // layer 3
    k_gemm3<<<(N_NODES + 7) / 8, 256>>>(a2h, a2l, W3);
    k_agg3<<<(N_NODES + 31) / 32, 256>>>(b3);
    k_log_softmax<<<(N_NODES + 255) / 256, 256>>>(out);
}

// round 15
// speedup vs baseline: 1.0551x; 1.0551x over previous
#include <cuda_runtime.h>
#include <cuda_bf16.h>
#include <stdint.h>
#include <math.h>

#define N_NODES 50000
#define NSPL    24960         // node split: 195 * 128
#define F_IN    1433
#define KP1     1440          // F_IN padded to 32 multiple
#define HDIM    256
#define NCLS    7
#define EDGES_MAX 800000
#define NSCAN_BLK 49          // ceil(50000/1024)

// ---------------- scratch (static device arrays; no cudaMalloc) ----------------
__device__ int   g_cnt[N_NODES];
__device__ int   g_off[N_NODES + 1];
__device__ int   g_cur[N_NODES];
__device__ int   g_bsum[64];
__device__ int   g_bsumx[64];
__device__ float g_dinv[N_NODES];
__device__ int2  g_csr[EDGES_MAX];

__device__ __align__(16) __nv_bfloat16 g_xh[(size_t)N_NODES * KP1];
__device__ __align__(16) __nv_bfloat16 g_xl[(size_t)N_NODES * KP1];
__device__ __align__(16) __nv_bfloat16 g_w1h[KP1 * HDIM];
__device__ __align__(16) __nv_bfloat16 g_w1l[KP1 * HDIM];
__device__ __align__(16) __nv_bfloat16 g_w2h[HDIM * HDIM];
__device__ __align__(16) __nv_bfloat16 g_w2l[HDIM * HDIM];
__device__ __align__(16) float g_h[(size_t)N_NODES * HDIM];
__device__ __align__(16) __nv_bfloat16 g_a1h[(size_t)N_NODES * HDIM];
__device__ __align__(16) __nv_bfloat16 g_a1l[(size_t)N_NODES * HDIM];
__device__ __align__(16) __nv_bfloat16 g_a2h[(size_t)N_NODES * HDIM];
__device__ __align__(16) __nv_bfloat16 g_a2l[(size_t)N_NODES * HDIM];
__device__ __align__(16) float g_h3[N_NODES * 8];
__device__ __align__(16) float g_a3[N_NODES * 8];

// ---------------- CSR build + parallel scan ----------------
__global__ void k_zero_cnt() {
    int i = blockIdx.x * blockDim.x + threadIdx.x;
    if (i < N_NODES) g_cnt[i] = 0;
}
__global__ void k_cnt_edges(const int* __restrict__ dst, int E) {
    int e = blockIdx.x * blockDim.x + threadIdx.x;
    if (e < E) atomicAdd(&g_cnt[dst[e]], 1);
}
__global__ void k_dinv() {
    int i = blockIdx.x * blockDim.x + threadIdx.x;
    if (i < N_NODES) g_dinv[i] = rsqrtf(1.0f + (float)g_cnt[i]);
}
__global__ __launch_bounds__(1024) void k_scan1() {
    __shared__ int wsum[32];
    int tid = threadIdx.x, lane = tid & 31, w = tid >> 5;
    int i = blockIdx.x * 1024 + tid;
    int v = (i < N_NODES) ? g_cnt[i] : 0;
    int x = v;
#pragma unroll
    for (int o = 1; o < 32; o <<= 1) {
        int y = __shfl_up_sync(~0u, x, o);
        if (lane >= o) x += y;
    }
    if (lane == 31) wsum[w] = x;
    __syncthreads();
    if (w == 0) {
        int s = wsum[lane];
#pragma unroll
        for (int o = 1; o < 32; o <<= 1) {
            int y = __shfl_up_sync(~0u, s, o);
            if (lane >= o) s += y;
        }
        wsum[lane] = s;
    }
    __syncthreads();
    int excl = x - v + (w ? wsum[w - 1] : 0);
    if (i < N_NODES) g_off[i] = excl;
    if (tid == 0) g_bsum[blockIdx.x] = wsum[31];
}
__global__ void k_scan2(int nb) {
    __shared__ int ws[2];
    int t = threadIdx.x, lane = t & 31, w = t >> 5;
    int v = (t < nb) ? g_bsum[t] : 0;
    int x = v;
#pragma unroll
    for (int o = 1; o < 32; o <<= 1) {
        int y = __shfl_up_sync(~0u, x, o);
        if (lane >= o) x += y;
    }
    if (lane == 31) ws[w] = x;
    __syncthreads();
    int incl = x + (w == 1 ? ws[0] : 0);
    if (t < 64) g_bsumx[t] = incl - v;
    if (t == 63) g_off[N_NODES] = ws[0] + ws[1];
}
__global__ __launch_bounds__(1024) void k_scan3() {
    int i = blockIdx.x * 1024 + threadIdx.x;
    if (i < N_NODES) {
        int o = g_off[i] + g_bsumx[i >> 10];
        g_off[i] = o;
        g_cur[i] = o;
    }
}
__global__ void k_csr_fill(const int* __restrict__ src, const int* __restrict__ dst, int E) {
    int e = blockIdx.x * blockDim.x + threadIdx.x;
    if (e >= E) return;
    int r = src[e], d = dst[e];
    int pos = atomicAdd(&g_cur[d], 1);
    g_csr[pos] = make_int2(r, __float_as_int(g_dinv[r] * g_dinv[d]));
}

// ---------------- operand prep: fp32 -> bf16 hi/lo ----------------
__device__ __forceinline__ void split4(const float v[4], unsigned h2[2], unsigned l2[2]) {
#pragma unroll
    for (int p = 0; p < 2; p++) {
        __nv_bfloat162 hb = __floats2bfloat162_rn(v[2 * p], v[2 * p + 1]);
        float2 hf = __bfloat1622float2(hb);
        __nv_bfloat162 lb = __floats2bfloat162_rn(v[2 * p] - hf.x, v[2 * p + 1] - hf.y);
        h2[p] = *reinterpret_cast<unsigned*>(&hb);
        l2[p] = *reinterpret_cast<unsigned*>(&lb);
    }
}
__global__ void k_split_x(const float* __restrict__ x) {
    long t = (long)blockIdx.x * blockDim.x + threadIdx.x;
    if (t >= (long)N_NODES * (KP1 / 4)) return;
    int row = (int)(t / (KP1 / 4));
    int k = (int)(t % (KP1 / 4)) * 4;
    float v[4];
#pragma unroll
    for (int j = 0; j < 4; j++)
        v[j] = (k + j < F_IN) ? __ldg(&x[(long)row * F_IN + k + j]) : 0.0f;
    unsigned h2[2], l2[2];
    split4(v, h2, l2);
    *reinterpret_cast<uint2*>(&g_xh[(long)row * KP1 + k]) = make_uint2(h2[0], h2[1]);
    *reinterpret_cast<uint2*>(&g_xl[(long)row * KP1 + k]) = make_uint2(l2[0], l2[1]);
}
__global__ void k_split_w(const float* __restrict__ W, __nv_bfloat16* __restrict__ Wh,
                          __nv_bfloat16* __restrict__ Wl, int K, int Kp) {
    int t = blockIdx.x * blockDim.x + threadIdx.x;
    if (t >= Kp * (HDIM / 4)) return;
    int k = t / (HDIM / 4);
    int n4 = t % (HDIM / 4);
    float v[4] = {0.f, 0.f, 0.f, 0.f};
    if (k < K) {
        float4 f = __ldg(reinterpret_cast<const float4*>(&W[(long)k * HDIM + n4 * 4]));
        v[0] = f.x; v[1] = f.y; v[2] = f.z; v[3] = f.w;
    }
    unsigned h2[2], l2[2];
    split4(v, h2, l2);
    *reinterpret_cast<uint2*>(&Wh[(long)k * HDIM + n4 * 4]) = make_uint2(h2[0], h2[1]);
    *reinterpret_cast<uint2*>(&Wl[(long)k * HDIM + n4 * 4]) = make_uint2(l2[0], l2[1]);
}

// =====================================================================
// bf16 split-precision tensor-core GEMM (R11-proven, frozen inner loop).
// =====================================================================
#define BM 128
#define BN 64
#define BK 32

__device__ __forceinline__ int swzA(int m, int c) {
    return (m >> 1) * 8 + ((((m & 1) * 4) + c) ^ ((m >> 1) & 7));
}
__device__ __forceinline__ int swzB(int k, int c) {
    return k * 8 + (c ^ (k & 7));
}
__device__ __forceinline__ void cp16(uint4* smem, const uint4* g, bool valid) {
    unsigned s = (unsigned)__cvta_generic_to_shared(smem);
    int sz = valid ? 16 : 0;
    asm volatile("cp.async.ca.shared.global [%0], [%1], 16, %2;"
                 :: "r"(s), "l"(g), "r"(sz));
}
__device__ __forceinline__ void cp_commit() { asm volatile("cp.async.commit_group;"); }
__device__ __forceinline__ void cp_wait_all() { asm volatile("cp.async.wait_group 0;"); }

__device__ __forceinline__ void ldsm_x4(unsigned r[4], const void* p) {
    unsigned a = (unsigned)__cvta_generic_to_shared(p);
    asm volatile("ldmatrix.sync.aligned.m8n8.x4.shared.b16 {%0,%1,%2,%3}, [%4];"
                 : "=r"(r[0]), "=r"(r[1]), "=r"(r[2]), "=r"(r[3]) : "r"(a));
}
__device__ __forceinline__ void ldsm_x4_t(unsigned r[4], const void* p) {
    unsigned a = (unsigned)__cvta_generic_to_shared(p);
    asm volatile("ldmatrix.sync.aligned.m8n8.x4.trans.shared.b16 {%0,%1,%2,%3}, [%4];"
                 : "=r"(r[0]), "=r"(r[1]), "=r"(r[2]), "=r"(r[3]) : "r"(a));
}
__device__ __forceinline__ void mma_bf16(float c[4], const unsigned a[4],
                                         unsigned b0, unsigned b1) {
    asm volatile(
        "mma.sync.aligned.m16n8k16.row.col.f32.bf16.bf16.f32 "
        "{%0,%1,%2,%3}, {%4,%5,%6,%7}, {%8,%9}, {%0,%1,%2,%3};"
        : "+f"(c[0]), "+f"(c[1]), "+f"(c[2]), "+f"(c[3])
        : "r"(a[0]), "r"(a[1]), "r"(a[2]), "r"(a[3]), "r"(b0), "r"(b1));
}

__global__ __launch_bounds__(256, 2)
void k_gemm_bf3(const __nv_bfloat16* __restrict__ Ah, const __nv_bfloat16* __restrict__ Al,
                const __nv_bfloat16* __restrict__ Bh_, const __nv_bfloat16* __restrict__ Bl_,
                float* __restrict__ C, int M, int Kp) {
    __shared__ uint4 sAh[2][512], sAl[2][512], sBh[2][256], sBl[2][256];

    const int tid = threadIdx.x, warp = tid >> 5, lane = tid & 31;
    const int m0 = blockIdx.y * BM, n0 = blockIdx.x * BN;
    const int wm = (warp >> 1) * 32, wn = (warp & 1) * 32;
    const int g = lane >> 2, tg = lane & 3;

    const uint4* Ah4 = reinterpret_cast<const uint4*>(Ah);
    const uint4* Al4 = reinterpret_cast<const uint4*>(Al);
    const uint4* Bh4 = reinterpret_cast<const uint4*>(Bh_);
    const uint4* Bl4 = reinterpret_cast<const uint4*>(Bl_);
    const int Kp4 = Kp >> 3;
    const int n08 = n0 >> 3;

    const int a_m = tid >> 2, a_c = tid & 3;
    const int b_k = tid >> 3, b_c = tid & 7;
    const int gm0 = m0 + a_m, gm1 = gm0 + 64;
    const bool v0 = gm0 < M, v1 = gm1 < M;
    const long aRow0 = (long)(v0 ? gm0 : 0) * Kp4;
    const long aRow1 = (long)(v1 ? gm1 : 0) * Kp4;
    const int sA0 = swzA(a_m, a_c), sA1 = swzA(a_m + 64, a_c);
    const int sB = swzB(b_k, b_c);

    auto issue = [&](int t, int buf) {
        long ac  = aRow0 + t * 4 + a_c;
        long ac1 = aRow1 + t * 4 + a_c;
        cp16(&sAh[buf][sA0], &Ah4[ac],  v0);
        cp16(&sAl[buf][sA0], &Al4[ac],  v0);
        cp16(&sAh[buf][sA1], &Ah4[ac1], v1);
        cp16(&sAl[buf][sA1], &Al4[ac1], v1);
        long bc = (long)(t * 32 + b_k) * (HDIM / 8) + n08 + b_c;
        cp16(&sBh[buf][sB], &Bh4[bc], true);
        cp16(&sBl[buf][sB], &Bl4[bc], true);
        cp_commit();
    };

    float acc[2][4][4];
#pragma unroll
    for (int i = 0; i < 2; i++)
#pragma unroll
        for (int j = 0; j < 4; j++)
#pragma unroll
            for (int r = 0; r < 4; r++) acc[i][j][r] = 0.0f;

    const int T = Kp / BK;
    issue(0, 0);
    for (int t = 0; t < T; t++) {
        cp_wait_all();
        __syncthreads();
        const int cur = t & 1;
        if (t + 1 < T) issue(t + 1, cur ^ 1);

#pragma unroll
        for (int ks = 0; ks < 2; ks++) {
            unsigned ah[2][4], al[2][4], bh[2][4], bl[2][4];
#pragma unroll
            for (int mi = 0; mi < 2; mi++) {
                int row = wm + mi * 16 + (lane & 15);
                int c = ks * 2 + (lane >> 4);
                ldsm_x4(ah[mi], &sAh[cur][swzA(row, c)]);
                ldsm_x4(al[mi], &sAl[cur][swzA(row, c)]);
            }
#pragma unroll
            for (int njp = 0; njp < 2; njp++) {
                int krow = ks * 16 + ((lane >> 3) & 1) * 8 + (lane & 7);
                int c = (wn >> 3) + 2 * njp + (lane >> 4);
                ldsm_x4_t(bh[njp], &sBh[cur][swzB(krow, c)]);
                ldsm_x4_t(bl[njp], &sBl[cur][swzB(krow, c)]);
            }
#pragma unroll
            for (int mi = 0; mi < 2; mi++)
#pragma unroll
                for (int njp = 0; njp < 2; njp++)
#pragma unroll
                    for (int sub = 0; sub < 2; sub++) {
                        int nj = njp * 2 + sub;
                        mma_bf16(acc[mi][nj], ah[mi], bh[njp][2*sub], bh[njp][2*sub+1]);
                        mma_bf16(acc[mi][nj], ah[mi], bl[njp][2*sub], bl[njp][2*sub+1]);
                        mma_bf16(acc[mi][nj], al[mi], bh[njp][2*sub], bh[njp][2*sub+1]);
                    }
        }
        __syncthreads();
    }

#pragma unroll
    for (int mi = 0; mi < 2; mi++) {
        int row0 = m0 + wm + mi * 16 + g;
        int row1 = row0 + 8;
#pragma unroll
        for (int nj = 0; nj < 4; nj++) {
            int col = n0 + wn + nj * 8 + tg * 2;
            if (row0 < M)
                *reinterpret_cast<float2*>(&C[(long)row0 * HDIM + col]) =
                    make_float2(acc[mi][nj][0], acc[mi][nj][1]);
            if (row1 < M)
                *reinterpret_cast<float2*>(&C[(long)row1 * HDIM + col]) =
                    make_float2(acc[mi][nj][2], acc[mi][nj][3]);
        }
    }
}

// ---------------- CSR aggregation (gather, node-range) ----------------
__global__ __launch_bounds__(128)
void k_agg(const float* __restrict__ h, const float* __restrict__ bias,
           __nv_bfloat16* __restrict__ oh, __nv_bfloat16* __restrict__ ol,
           int node0, int nend) {
    int node = node0 + blockIdx.x * 2 + (threadIdx.x >> 6);
    int f4 = threadIdx.x & 63;
    if (node >= nend) return;
    float d = g_dinv[node];
    float s = d * d;
    float4 acc = __ldg(reinterpret_cast<const float4*>(bias) + f4);
    float4 hv = __ldg(reinterpret_cast<const float4*>(h + (long)node * HDIM) + f4);
    acc.x += s * hv.x; acc.y += s * hv.y; acc.z += s * hv.z; acc.w += s * hv.w;
    int st = g_off[node], en = g_off[node + 1];
    for (int i = st; i < en; i++) {
        int2 ent = __ldg(&g_csr[i]);
        float nrm = __int_as_float(ent.y);
        float4 v = __ldg(reinterpret_cast<const float4*>(h + (long)ent.x * HDIM) + f4);
        acc.x += nrm * v.x; acc.y += nrm * v.y; acc.z += nrm * v.z; acc.w += nrm * v.w;
    }
    float v[4] = { fmaxf(acc.x, 0.f), fmaxf(acc.y, 0.f), fmaxf(acc.z, 0.f), fmaxf(acc.w, 0.f) };
    unsigned h2[2], l2[2];
    split4(v, h2, l2);
    *reinterpret_cast<uint2*>(&oh[(long)node * HDIM + f4 * 4]) = make_uint2(h2[0], h2[1]);
    *reinterpret_cast<uint2*>(&ol[(long)node * HDIM + f4 * 4]) = make_uint2(l2[0], l2[1]);
}

// ---------------- layer 3 (row-range) ----------------
__global__ __launch_bounds__(256)
void k_gemm3(const __nv_bfloat16* __restrict__ Ahd, const __nv_bfloat16* __restrict__ Ald,
             const float* __restrict__ W, int base, int rend) {
    __shared__ float Ws[HDIM * NCLS];
    int tid = threadIdx.x;
    for (int i = tid; i < HDIM * NCLS; i += 256) Ws[i] = W[i];
    __syncthreads();
    int warp = tid >> 5, lane = tid & 31;
    int row = base + blockIdx.x * 8 + warp;
    if (row >= rend) return;
    uint4 uh = __ldg(reinterpret_cast<const uint4*>(Ahd + (long)row * HDIM) + lane);
    uint4 ul = __ldg(reinterpret_cast<const uint4*>(Ald + (long)row * HDIM) + lane);
    float v[8];
    const unsigned* hu = reinterpret_cast<const unsigned*>(&uh);
    const unsigned* lu = reinterpret_cast<const unsigned*>(&ul);
#pragma unroll
    for (int p = 0; p < 4; p++) {
        float2 hf = __bfloat1622float2(*reinterpret_cast<const __nv_bfloat162*>(&hu[p]));
        float2 lf = __bfloat1622float2(*reinterpret_cast<const __nv_bfloat162*>(&lu[p]));
        v[2*p] = hf.x + lf.x; v[2*p+1] = hf.y + lf.y;
    }
    int k0 = lane * 8;
    float acc[NCLS];
#pragma unroll
    for (int c = 0; c < NCLS; c++) acc[c] = 0.0f;
#pragma unroll
    for (int j = 0; j < 8; j++)
#pragma unroll
        for (int c = 0; c < NCLS; c++)
            acc[c] = fmaf(v[j], Ws[(k0 + j) * NCLS + c], acc[c]);
#pragma unroll
    for (int c = 0; c < NCLS; c++)
#pragma unroll
        for (int off = 16; off; off >>= 1)
            acc[c] += __shfl_down_sync(0xffffffffu, acc[c], off);
    if (lane == 0) {
#pragma unroll
        for (int c = 0; c < NCLS; c++) g_h3[row * 8 + c] = acc[c];
        g_h3[row * 8 + 7] = 0.0f;
    }
}
__global__ __launch_bounds__(256)
void k_agg3(const float* __restrict__ b3) {
    int node = blockIdx.x * 32 + (threadIdx.x >> 3);
    int c = threadIdx.x & 7;
    if (node >= N_NODES || c >= NCLS) return;
    float d = g_dinv[node];
    float acc = b3[c] + d * d * g_h3[node * 8 + c];
    int st = g_off[node], en = g_off[node + 1];
    for (int i = st; i < en; i++) {
        int2 ent = __ldg(&g_csr[i]);
        acc += __int_as_float(ent.y) * g_h3[ent.x * 8 + c];
    }
    g_a3[node * 8 + c] = acc;
}
__global__ void k_log_softmax(float* __restrict__ out) {
    int i = blockIdx.x * blockDim.x + threadIdx.x;
    if (i >= N_NODES) return;
    float v[NCLS];
    float m = -INFINITY;
#pragma unroll
    for (int c = 0; c < NCLS; c++) { v[c] = g_a3[i * 8 + c]; m = fmaxf(m, v[c]); }
    float s = 0.0f;
#pragma unroll
    for (int c = 0; c < NCLS; c++) s += __expf(v[c] - m);
    float lse = m + __logf(s);
#pragma unroll
    for (int c = 0; c < NCLS; c++) out[i * NCLS + c] = v[c] - lse;
}

// ---------------- launch (two-stream fork/join inside capture) ----------------
extern "C" void kernel_launch(void* const* d_in, const int* in_sizes, int n_in,
                              void* d_out, int out_size) {
    const float* x  = (const float*)d_in[0];
    const int*   ei = (const int*)d_in[1];
    const float* W1 = (const float*)d_in[2];
    const float* b1 = (const float*)d_in[3];
    const float* W2 = (const float*)d_in[4];
    const float* b2 = (const float*)d_in[5];
    const float* W3 = (const float*)d_in[6];
    const float* b3 = (const float*)d_in[7];
    float* out = (float*)d_out;

    const int E = in_sizes[1] / 2;
    const int* src = ei;
    const int* dst = ei + E;

    __nv_bfloat16 *xh, *xl, *w1h, *w1l, *w2h, *w2l, *a1h, *a1l, *a2h, *a2l;
    float* gh;
    cudaGetSymbolAddress((void**)&xh, g_xh);   cudaGetSymbolAddress((void**)&xl, g_xl);
    cudaGetSymbolAddress((void**)&w1h, g_w1h); cudaGetSymbolAddress((void**)&w1l, g_w1l);
    cudaGetSymbolAddress((void**)&w2h, g_w2h); cudaGetSymbolAddress((void**)&w2l, g_w2l);
    cudaGetSymbolAddress((void**)&a1h, g_a1h); cudaGetSymbolAddress((void**)&a1l, g_a1l);
    cudaGetSymbolAddress((void**)&a2h, g_a2h); cudaGetSymbolAddress((void**)&a2l, g_a2l);
    cudaGetSymbolAddress((void**)&gh, g_h);

    static cudaStream_t s2 = nullptr;
    static cudaEvent_t evFork = nullptr, evCSR = nullptr, evW2 = nullptr,
                       evG1 = nullptr, evG2 = nullptr, evA1b = nullptr, evA2b = nullptr;
    if (!s2) {
        cudaStreamCreateWithFlags(&s2, cudaStreamNonBlocking);
        cudaEventCreateWithFlags(&evFork, cudaEventDisableTiming);
        cudaEventCreateWithFlags(&evCSR, cudaEventDisableTiming);
        cudaEventCreateWithFlags(&evW2, cudaEventDisableTiming);
        cudaEventCreateWithFlags(&evG1, cudaEventDisableTiming);
        cudaEventCreateWithFlags(&evG2, cudaEventDisableTiming);
        cudaEventCreateWithFlags(&evA1b, cudaEventDisableTiming);
        cudaEventCreateWithFlags(&evA2b, cudaEventDisableTiming);
    }

    // ---- fork
    cudaEventRecord(evFork, 0);
    cudaStreamWaitEvent(s2, evFork, 0);

    // side stream: CSR chain + W2 split
    k_zero_cnt<<<(N_NODES + 255) / 256, 256, 0, s2>>>();
    k_cnt_edges<<<(E + 255) / 256, 256, 0, s2>>>(dst, E);
    k_dinv<<<(N_NODES + 255) / 256, 256, 0, s2>>>();
    k_scan1<<<NSCAN_BLK, 1024, 0, s2>>>();
    k_scan2<<<1, 64, 0, s2>>>(NSCAN_BLK);
    k_scan3<<<NSCAN_BLK, 1024, 0, s2>>>();
    k_csr_fill<<<(E + 255) / 256, 256, 0, s2>>>(src, dst, E);
    cudaEventRecord(evCSR, s2);
    k_split_w<<<(HDIM * 64 + 255) / 256, 256, 0, s2>>>(W2, w2h, w2l, HDIM, HDIM);
    cudaEventRecord(evW2, s2);

    // main stream: prep + GEMM1 (full)
    {
        long tx = (long)N_NODES * (KP1 / 4);
        k_split_x<<<(unsigned)((tx + 255) / 256), 256>>>(x);
        k_split_w<<<(KP1 * 64 + 255) / 256, 256>>>(W1, w1h, w1l, F_IN, KP1);
    }
    dim3 grid_full(HDIM / BN, (N_NODES + BM - 1) / BM);
    k_gemm_bf3<<<grid_full, 256>>>(xh, xl, w1h, w1l, gh, N_NODES, KP1);
    cudaEventRecord(evG1, 0);

    // side: agg1b (nodes [NSPL, N)) — needs GEMM1 + own CSR
    cudaStreamWaitEvent(s2, evG1, 0);
    k_agg<<<(N_NODES - NSPL + 1) / 2, 128, 0, s2>>>(gh, b1, a1h, a1l, NSPL, N_NODES);
    cudaEventRecord(evA1b, s2);

    // main: agg1a (nodes [0, NSPL)) — needs CSR from side
    cudaStreamWaitEvent(0, evCSR, 0);
    k_agg<<<(NSPL + 1) / 2, 128>>>(gh, b1, a1h, a1l, 0, NSPL);

    // main: GEMM2a (rows [0, NSPL)) — needs w2 and agg1a
    cudaStreamWaitEvent(0, evW2, 0);
    dim3 grid2a(HDIM / BN, NSPL / BM);
    k_gemm_bf3<<<grid2a, 256>>>(a1h, a1l, w2h, w2l, gh, NSPL, HDIM);

    // main: GEMM2b (rows [NSPL, N)) — needs agg1b from side
    cudaStreamWaitEvent(0, evA1b, 0);
    dim3 grid2b(HDIM / BN, (N_NODES - NSPL + BM - 1) / BM);
    k_gemm_bf3<<<grid2b, 256>>>(a1h + (size_t)NSPL * HDIM, a1l + (size_t)NSPL * HDIM,
                                w2h, w2l, gh + (size_t)NSPL * HDIM,
                                N_NODES - NSPL, HDIM);
    cudaEventRecord(evG2, 0);

    // side: agg2b (nodes [NSPL, N)) — needs full h from GEMM2a+2b
    cudaStreamWaitEvent(s2, evG2, 0);
    k_agg<<<(N_NODES - NSPL + 1) / 2, 128, 0, s2>>>(gh, b2, a2h, a2l, NSPL, N_NODES);
    cudaEventRecord(evA2b, s2);

    // main: agg2a + gemm3a (rows [0, NSPL))
    k_agg<<<(NSPL + 1) / 2, 128>>>(gh, b2, a2h, a2l, 0, NSPL);
    k_gemm3<<<NSPL / 8, 256>>>(a2h, a2l, W3, 0, NSPL);

    // main: gemm3b — needs agg2b
    cudaStreamWaitEvent(0, evA2b, 0);
    k_gemm3<<<(N_NODES - NSPL + 7) / 8, 256>>>(a2h, a2l, W3, NSPL, N_NODES);

    // tail
    k_agg3<<<(N_NODES + 31) / 32, 256>>>(b3);
    k_log_softmax<<<(N_NODES + 255) / 256, 256>>>(out);
}

// round 16
// speedup vs baseline: 1.0783x; 1.0220x over previous
#include <cuda_runtime.h>
#include <cuda_bf16.h>
#include <stdint.h>
#include <math.h>

#define N_NODES 50000
#define F_IN    1433
#define KP1     1440          // F_IN padded to 32 multiple
#define HDIM    256
#define NCLS    7
#define EDGES_MAX 800000
#define NSCAN_BLK 49          // ceil(50000/1024)

// ---------------- scratch (static device arrays; no cudaMalloc) ----------------
__device__ int   g_cnt[N_NODES];
__device__ int   g_off[N_NODES + 1];
__device__ int   g_cur[N_NODES];
__device__ int   g_bsum[64];
__device__ int   g_bsumx[64];
__device__ float g_dinv[N_NODES];
__device__ int2  g_csr[EDGES_MAX];

__device__ __align__(16) __nv_bfloat16 g_xh[(size_t)N_NODES * KP1];
__device__ __align__(16) __nv_bfloat16 g_xl[(size_t)N_NODES * KP1];
__device__ __align__(16) __nv_bfloat16 g_w1h[KP1 * HDIM];
__device__ __align__(16) __nv_bfloat16 g_w1l[KP1 * HDIM];
__device__ __align__(16) __nv_bfloat16 g_w2h[HDIM * HDIM];
__device__ __align__(16) __nv_bfloat16 g_w2l[HDIM * HDIM];
__device__ __align__(16) float g_h[(size_t)N_NODES * HDIM];
__device__ __align__(16) __nv_bfloat16 g_a1h[(size_t)N_NODES * HDIM];
__device__ __align__(16) __nv_bfloat16 g_a1l[(size_t)N_NODES * HDIM];
__device__ __align__(16) __nv_bfloat16 g_a2h[(size_t)N_NODES * HDIM];
__device__ __align__(16) __nv_bfloat16 g_a2l[(size_t)N_NODES * HDIM];
__device__ __align__(16) float g_h3[N_NODES * 8];

// ---------------- CSR build + parallel scan ----------------
__global__ void k_zero_cnt() {
    int i = blockIdx.x * blockDim.x + threadIdx.x;
    if (i < N_NODES) g_cnt[i] = 0;
}
__global__ void k_cnt_edges(const int* __restrict__ dst, int E) {
    int e = blockIdx.x * blockDim.x + threadIdx.x;
    if (e < E) atomicAdd(&g_cnt[dst[e]], 1);
}
__global__ void k_dinv() {
    int i = blockIdx.x * blockDim.x + threadIdx.x;
    if (i < N_NODES) g_dinv[i] = rsqrtf(1.0f + (float)g_cnt[i]);
}
__global__ __launch_bounds__(1024) void k_scan1() {
    __shared__ int wsum[32];
    int tid = threadIdx.x, lane = tid & 31, w = tid >> 5;
    int i = blockIdx.x * 1024 + tid;
    int v = (i < N_NODES) ? g_cnt[i] : 0;
    int x = v;
#pragma unroll
    for (int o = 1; o < 32; o <<= 1) {
        int y = __shfl_up_sync(~0u, x, o);
        if (lane >= o) x += y;
    }
    if (lane == 31) wsum[w] = x;
    __syncthreads();
    if (w == 0) {
        int s = wsum[lane];
#pragma unroll
        for (int o = 1; o < 32; o <<= 1) {
            int y = __shfl_up_sync(~0u, s, o);
            if (lane >= o) s += y;
        }
        wsum[lane] = s;
    }
    __syncthreads();
    int excl = x - v + (w ? wsum[w - 1] : 0);
    if (i < N_NODES) g_off[i] = excl;
    if (tid == 0) g_bsum[blockIdx.x] = wsum[31];
}
__global__ void k_scan2(int nb) {
    __shared__ int ws[2];
    int t = threadIdx.x, lane = t & 31, w = t >> 5;
    int v = (t < nb) ? g_bsum[t] : 0;
    int x = v;
#pragma unroll
    for (int o = 1; o < 32; o <<= 1) {
        int y = __shfl_up_sync(~0u, x, o);
        if (lane >= o) x += y;
    }
    if (lane == 31) ws[w] = x;
    __syncthreads();
    int incl = x + (w == 1 ? ws[0] : 0);
    if (t < 64) g_bsumx[t] = incl - v;
    if (t == 63) g_off[N_NODES] = ws[0] + ws[1];
}
__global__ __launch_bounds__(1024) void k_scan3() {
    int i = blockIdx.x * 1024 + threadIdx.x;
    if (i < N_NODES) {
        int o = g_off[i] + g_bsumx[i >> 10];
        g_off[i] = o;
        g_cur[i] = o;
    }
}
__global__ void k_csr_fill(const int* __restrict__ src, const int* __restrict__ dst, int E) {
    int e = blockIdx.x * blockDim.x + threadIdx.x;
    if (e >= E) return;
    int r = src[e], d = dst[e];
    int pos = atomicAdd(&g_cur[d], 1);
    g_csr[pos] = make_int2(r, __float_as_int(g_dinv[r] * g_dinv[d]));
}

// ---------------- operand prep: fp32 -> bf16 hi/lo ----------------
__device__ __forceinline__ void split4(const float v[4], unsigned h2[2], unsigned l2[2]) {
#pragma unroll
    for (int p = 0; p < 2; p++) {
        __nv_bfloat162 hb = __floats2bfloat162_rn(v[2 * p], v[2 * p + 1]);
        float2 hf = __bfloat1622float2(hb);
        __nv_bfloat162 lb = __floats2bfloat162_rn(v[2 * p] - hf.x, v[2 * p + 1] - hf.y);
        h2[p] = *reinterpret_cast<unsigned*>(&hb);
        l2[p] = *reinterpret_cast<unsigned*>(&lb);
    }
}
__global__ void k_split_x(const float* __restrict__ x) {
    long t = (long)blockIdx.x * blockDim.x + threadIdx.x;
    if (t >= (long)N_NODES * (KP1 / 4)) return;
    int row = (int)(t / (KP1 / 4));
    int k = (int)(t % (KP1 / 4)) * 4;
    float v[4];
#pragma unroll
    for (int j = 0; j < 4; j++)
        v[j] = (k + j < F_IN) ? __ldg(&x[(long)row * F_IN + k + j]) : 0.0f;
    unsigned h2[2], l2[2];
    split4(v, h2, l2);
    *reinterpret_cast<uint2*>(&g_xh[(long)row * KP1 + k]) = make_uint2(h2[0], h2[1]);
    *reinterpret_cast<uint2*>(&g_xl[(long)row * KP1 + k]) = make_uint2(l2[0], l2[1]);
}
__global__ void k_split_w(const float* __restrict__ W, __nv_bfloat16* __restrict__ Wh,
                          __nv_bfloat16* __restrict__ Wl, int K, int Kp) {
    int t = blockIdx.x * blockDim.x + threadIdx.x;
    if (t >= Kp * (HDIM / 4)) return;
    int k = t / (HDIM / 4);
    int n4 = t % (HDIM / 4);
    float v[4] = {0.f, 0.f, 0.f, 0.f};
    if (k < K) {
        float4 f = __ldg(reinterpret_cast<const float4*>(&W[(long)k * HDIM + n4 * 4]));
        v[0] = f.x; v[1] = f.y; v[2] = f.z; v[3] = f.w;
    }
    unsigned h2[2], l2[2];
    split4(v, h2, l2);
    *reinterpret_cast<uint2*>(&Wh[(long)k * HDIM + n4 * 4]) = make_uint2(h2[0], h2[1]);
    *reinterpret_cast<uint2*>(&Wl[(long)k * HDIM + n4 * 4]) = make_uint2(l2[0], l2[1]);
}

// =====================================================================
// bf16 split-precision tensor-core GEMM (R11-proven, frozen inner loop).
// =====================================================================
#define BM 128
#define BN 64
#define BK 32

__device__ __forceinline__ int swzA(int m, int c) {
    return (m >> 1) * 8 + ((((m & 1) * 4) + c) ^ ((m >> 1) & 7));
}
__device__ __forceinline__ int swzB(int k, int c) {
    return k * 8 + (c ^ (k & 7));
}
__device__ __forceinline__ void cp16(uint4* smem, const uint4* g, bool valid) {
    unsigned s = (unsigned)__cvta_generic_to_shared(smem);
    int sz = valid ? 16 : 0;
    asm volatile("cp.async.ca.shared.global [%0], [%1], 16, %2;"
                 :: "r"(s), "l"(g), "r"(sz));
}
__device__ __forceinline__ void cp_commit() { asm volatile("cp.async.commit_group;"); }
__device__ __forceinline__ void cp_wait_all() { asm volatile("cp.async.wait_group 0;"); }

__device__ __forceinline__ void ldsm_x4(unsigned r[4], const void* p) {
    unsigned a = (unsigned)__cvta_generic_to_shared(p);
    asm volatile("ldmatrix.sync.aligned.m8n8.x4.shared.b16 {%0,%1,%2,%3}, [%4];"
                 : "=r"(r[0]), "=r"(r[1]), "=r"(r[2]), "=r"(r[3]) : "r"(a));
}
__device__ __forceinline__ void ldsm_x4_t(unsigned r[4], const void* p) {
    unsigned a = (unsigned)__cvta_generic_to_shared(p);
    asm volatile("ldmatrix.sync.aligned.m8n8.x4.trans.shared.b16 {%0,%1,%2,%3}, [%4];"
                 : "=r"(r[0]), "=r"(r[1]), "=r"(r[2]), "=r"(r[3]) : "r"(a));
}
__device__ __forceinline__ void mma_bf16(float c[4], const unsigned a[4],
                                         unsigned b0, unsigned b1) {
    asm volatile(
        "mma.sync.aligned.m16n8k16.row.col.f32.bf16.bf16.f32 "
        "{%0,%1,%2,%3}, {%4,%5,%6,%7}, {%8,%9}, {%0,%1,%2,%3};"
        : "+f"(c[0]), "+f"(c[1]), "+f"(c[2]), "+f"(c[3])
        : "r"(a[0]), "r"(a[1]), "r"(a[2]), "r"(a[3]), "r"(b0), "r"(b1));
}

__global__ __launch_bounds__(256, 2)
void k_gemm_bf3(const __nv_bfloat16* __restrict__ Ah, const __nv_bfloat16* __restrict__ Al,
                const __nv_bfloat16* __restrict__ Bh_, const __nv_bfloat16* __restrict__ Bl_,
                float* __restrict__ C, int M, int Kp) {
    __shared__ uint4 sAh[2][512], sAl[2][512], sBh[2][256], sBl[2][256];

    const int tid = threadIdx.x, warp = tid >> 5, lane = tid & 31;
    const int m0 = blockIdx.y * BM, n0 = blockIdx.x * BN;
    const int wm = (warp >> 1) * 32, wn = (warp & 1) * 32;
    const int g = lane >> 2, tg = lane & 3;

    const uint4* Ah4 = reinterpret_cast<const uint4*>(Ah);
    const uint4* Al4 = reinterpret_cast<const uint4*>(Al);
    const uint4* Bh4 = reinterpret_cast<const uint4*>(Bh_);
    const uint4* Bl4 = reinterpret_cast<const uint4*>(Bl_);
    const int Kp4 = Kp >> 3;
    const int n08 = n0 >> 3;

    const int a_m = tid >> 2, a_c = tid & 3;
    const int b_k = tid >> 3, b_c = tid & 7;
    const int gm0 = m0 + a_m, gm1 = gm0 + 64;
    const bool v0 = gm0 < M, v1 = gm1 < M;
    const long aRow0 = (long)(v0 ? gm0 : 0) * Kp4;
    const long aRow1 = (long)(v1 ? gm1 : 0) * Kp4;
    const int sA0 = swzA(a_m, a_c), sA1 = swzA(a_m + 64, a_c);
    const int sB = swzB(b_k, b_c);

    auto issue = [&](int t, int buf) {
        long ac  = aRow0 + t * 4 + a_c;
        long ac1 = aRow1 + t * 4 + a_c;
        cp16(&sAh[buf][sA0], &Ah4[ac],  v0);
        cp16(&sAl[buf][sA0], &Al4[ac],  v0);
        cp16(&sAh[buf][sA1], &Ah4[ac1], v1);
        cp16(&sAl[buf][sA1], &Al4[ac1], v1);
        long bc = (long)(t * 32 + b_k) * (HDIM / 8) + n08 + b_c;
        cp16(&sBh[buf][sB], &Bh4[bc], true);
        cp16(&sBl[buf][sB], &Bl4[bc], true);
        cp_commit();
    };

    float acc[2][4][4];
#pragma unroll
    for (int i = 0; i < 2; i++)
#pragma unroll
        for (int j = 0; j < 4; j++)
#pragma unroll
            for (int r = 0; r < 4; r++) acc[i][j][r] = 0.0f;

    const int T = Kp / BK;
    issue(0, 0);
    for (int t = 0; t < T; t++) {
        cp_wait_all();
        __syncthreads();
        const int cur = t & 1;
        if (t + 1 < T) issue(t + 1, cur ^ 1);

#pragma unroll
        for (int ks = 0; ks < 2; ks++) {
            unsigned ah[2][4], al[2][4], bh[2][4], bl[2][4];
#pragma unroll
            for (int mi = 0; mi < 2; mi++) {
                int row = wm + mi * 16 + (lane & 15);
                int c = ks * 2 + (lane >> 4);
                ldsm_x4(ah[mi], &sAh[cur][swzA(row, c)]);
                ldsm_x4(al[mi], &sAl[cur][swzA(row, c)]);
            }
#pragma unroll
            for (int njp = 0; njp < 2; njp++) {
                int krow = ks * 16 + ((lane >> 3) & 1) * 8 + (lane & 7);
                int c = (wn >> 3) + 2 * njp + (lane >> 4);
                ldsm_x4_t(bh[njp], &sBh[cur][swzB(krow, c)]);
                ldsm_x4_t(bl[njp], &sBl[cur][swzB(krow, c)]);
            }
#pragma unroll
            for (int mi = 0; mi < 2; mi++)
#pragma unroll
                for (int njp = 0; njp < 2; njp++)
#pragma unroll
                    for (int sub = 0; sub < 2; sub++) {
                        int nj = njp * 2 + sub;
                        mma_bf16(acc[mi][nj], ah[mi], bh[njp][2*sub], bh[njp][2*sub+1]);
                        mma_bf16(acc[mi][nj], ah[mi], bl[njp][2*sub], bl[njp][2*sub+1]);
                        mma_bf16(acc[mi][nj], al[mi], bh[njp][2*sub], bh[njp][2*sub+1]);
                    }
        }
        __syncthreads();
    }

#pragma unroll
    for (int mi = 0; mi < 2; mi++) {
        int row0 = m0 + wm + mi * 16 + g;
        int row1 = row0 + 8;
#pragma unroll
        for (int nj = 0; nj < 4; nj++) {
            int col = n0 + wn + nj * 8 + tg * 2;
            if (row0 < M)
                *reinterpret_cast<float2*>(&C[(long)row0 * HDIM + col]) =
                    make_float2(acc[mi][nj][0], acc[mi][nj][1]);
            if (row1 < M)
                *reinterpret_cast<float2*>(&C[(long)row1 * HDIM + col]) =
                    make_float2(acc[mi][nj][2], acc[mi][nj][3]);
        }
    }
}

// ---------------- CSR aggregation (gather, no atomics) ----------------
__global__ __launch_bounds__(128)
void k_agg(const float* __restrict__ h, const float* __restrict__ bias,
           __nv_bfloat16* __restrict__ oh, __nv_bfloat16* __restrict__ ol) {
    int node = blockIdx.x * 2 + (threadIdx.x >> 6);
    int f4 = threadIdx.x & 63;
    if (node >= N_NODES) return;
    float d = g_dinv[node];
    float s = d * d;
    float4 acc = __ldg(reinterpret_cast<const float4*>(bias) + f4);
    float4 hv = __ldg(reinterpret_cast<const float4*>(h + (long)node * HDIM) + f4);
    acc.x += s * hv.x; acc.y += s * hv.y; acc.z += s * hv.z; acc.w += s * hv.w;
    int st = g_off[node], en = g_off[node + 1];
    for (int i = st; i < en; i++) {
        int2 ent = __ldg(&g_csr[i]);
        float nrm = __int_as_float(ent.y);
        float4 v = __ldg(reinterpret_cast<const float4*>(h + (long)ent.x * HDIM) + f4);
        acc.x += nrm * v.x; acc.y += nrm * v.y; acc.z += nrm * v.z; acc.w += nrm * v.w;
    }
    float v[4] = { fmaxf(acc.x, 0.f), fmaxf(acc.y, 0.f), fmaxf(acc.z, 0.f), fmaxf(acc.w, 0.f) };
    unsigned h2[2], l2[2];
    split4(v, h2, l2);
    *reinterpret_cast<uint2*>(&oh[(long)node * HDIM + f4 * 4]) = make_uint2(h2[0], h2[1]);
    *reinterpret_cast<uint2*>(&ol[(long)node * HDIM + f4 * 4]) = make_uint2(l2[0], l2[1]);
}

// ---------------- layer 3 ----------------
__global__ __launch_bounds__(256)
void k_gemm3(const __nv_bfloat16* __restrict__ Ahd, const __nv_bfloat16* __restrict__ Ald,
             const float* __restrict__ W) {
    __shared__ float Ws[HDIM * NCLS];
    int tid = threadIdx.x;
    for (int i = tid; i < HDIM * NCLS; i += 256) Ws[i] = W[i];
    __syncthreads();
    int warp = tid >> 5, lane = tid & 31;
    int row = blockIdx.x * 8 + warp;
    if (row >= N_NODES) return;
    uint4 uh = __ldg(reinterpret_cast<const uint4*>(Ahd + (long)row * HDIM) + lane);
    uint4 ul = __ldg(reinterpret_cast<const uint4*>(Ald + (long)row * HDIM) + lane);
    float v[8];
    const unsigned* hu = reinterpret_cast<const unsigned*>(&uh);
    const unsigned* lu = reinterpret_cast<const unsigned*>(&ul);
#pragma unroll
    for (int p = 0; p < 4; p++) {
        float2 hf = __bfloat1622float2(*reinterpret_cast<const __nv_bfloat162*>(&hu[p]));
        float2 lf = __bfloat1622float2(*reinterpret_cast<const __nv_bfloat162*>(&lu[p]));
        v[2*p] = hf.x + lf.x; v[2*p+1] = hf.y + lf.y;
    }
    int k0 = lane * 8;
    float acc[NCLS];
#pragma unroll
    for (int c = 0; c < NCLS; c++) acc[c] = 0.0f;
#pragma unroll
    for (int j = 0; j < 8; j++)
#pragma unroll
        for (int c = 0; c < NCLS; c++)
            acc[c] = fmaf(v[j], Ws[(k0 + j) * NCLS + c], acc[c]);
#pragma unroll
    for (int c = 0; c < NCLS; c++)
#pragma unroll
        for (int off = 16; off; off >>= 1)
            acc[c] += __shfl_down_sync(0xffffffffu, acc[c], off);
    if (lane == 0) {
#pragma unroll
        for (int c = 0; c < NCLS; c++) g_h3[row * 8 + c] = acc[c];
        g_h3[row * 8 + 7] = 0.0f;
    }
}

// fused agg3 + log_softmax: 8 threads per node (aligned group), c = 0..7 (7 = pad)
__global__ __launch_bounds__(256)
void k_agg3_softmax(const float* __restrict__ b3, float* __restrict__ out) {
    int node = blockIdx.x * 32 + (threadIdx.x >> 3);
    int c = threadIdx.x & 7;
    if (node >= N_NODES) return;
    float acc;
    if (c < NCLS) {
        float d = g_dinv[node];
        acc = b3[c] + d * d * g_h3[node * 8 + c];
        int st = g_off[node], en = g_off[node + 1];
        for (int i = st; i < en; i++) {
            int2 ent = __ldg(&g_csr[i]);
            acc += __int_as_float(ent.y) * g_h3[ent.x * 8 + c];
        }
    } else {
        acc = -INFINITY;
    }
    // group-of-8 max (xor 1,2,4 stays within the aligned 8-lane group)
    float m = acc;
#pragma unroll
    for (int off = 4; off; off >>= 1)
        m = fmaxf(m, __shfl_xor_sync(0xffffffffu, m, off));
    float e = (c < NCLS) ? __expf(acc - m) : 0.0f;
    float s = e;
#pragma unroll
    for (int off = 4; off; off >>= 1)
        s += __shfl_xor_sync(0xffffffffu, s, off);
    float lse = m + __logf(s);
    if (c < NCLS) out[node * NCLS + c] = acc - lse;
}

// ---------------- launch (two-stream fork/join inside capture) ----------------
extern "C" void kernel_launch(void* const* d_in, const int* in_sizes, int n_in,
                              void* d_out, int out_size) {
    const float* x  = (const float*)d_in[0];
    const int*   ei = (const int*)d_in[1];
    const float* W1 = (const float*)d_in[2];
    const float* b1 = (const float*)d_in[3];
    const float* W2 = (const float*)d_in[4];
    const float* b2 = (const float*)d_in[5];
    const float* W3 = (const float*)d_in[6];
    const float* b3 = (const float*)d_in[7];
    float* out = (float*)d_out;

    const int E = in_sizes[1] / 2;
    const int* src = ei;
    const int* dst = ei + E;

    __nv_bfloat16 *xh, *xl, *w1h, *w1l, *w2h, *w2l, *a1h, *a1l, *a2h, *a2l;
    float* gh;
    cudaGetSymbolAddress((void**)&xh, g_xh);   cudaGetSymbolAddress((void**)&xl, g_xl);
    cudaGetSymbolAddress((void**)&w1h, g_w1h); cudaGetSymbolAddress((void**)&w1l, g_w1l);
    cudaGetSymbolAddress((void**)&w2h, g_w2h); cudaGetSymbolAddress((void**)&w2l, g_w2l);
    cudaGetSymbolAddress((void**)&a1h, g_a1h); cudaGetSymbolAddress((void**)&a1l, g_a1l);
    cudaGetSymbolAddress((void**)&a2h, g_a2h); cudaGetSymbolAddress((void**)&a2l, g_a2l);
    cudaGetSymbolAddress((void**)&gh, g_h);

    // one-time host resources (created on the uncaptured correctness call)
    static cudaStream_t s2 = nullptr;
    static cudaEvent_t evFork = nullptr, evW1 = nullptr, evJoin = nullptr;
    if (!s2) {
        cudaStreamCreateWithFlags(&s2, cudaStreamNonBlocking);
        cudaEventCreateWithFlags(&evFork, cudaEventDisableTiming);
        cudaEventCreateWithFlags(&evW1, cudaEventDisableTiming);
        cudaEventCreateWithFlags(&evJoin, cudaEventDisableTiming);
    }

    // ---- fork
    cudaEventRecord(evFork, 0);
    cudaStreamWaitEvent(s2, evFork, 0);

    // side stream: W1 split first (needed by GEMM1, covered by split_x time),
    // then CSR chain + W2 split (needed by agg1 / GEMM2, much later)
    k_split_w<<<(KP1 * 64 + 255) / 256, 256, 0, s2>>>(W1, w1h, w1l, F_IN, KP1);
    cudaEventRecord(evW1, s2);
    k_zero_cnt<<<(N_NODES + 255) / 256, 256, 0, s2>>>();
    k_cnt_edges<<<(E + 255) / 256, 256, 0, s2>>>(dst, E);
    k_dinv<<<(N_NODES + 255) / 256, 256, 0, s2>>>();
    k_scan1<<<NSCAN_BLK, 1024, 0, s2>>>();
    k_scan2<<<1, 64, 0, s2>>>(NSCAN_BLK);
    k_scan3<<<NSCAN_BLK, 1024, 0, s2>>>();
    k_csr_fill<<<(E + 255) / 256, 256, 0, s2>>>(src, dst, E);
    k_split_w<<<(HDIM * 64 + 255) / 256, 256, 0, s2>>>(W2, w2h, w2l, HDIM, HDIM);
    cudaEventRecord(evJoin, s2);

    // main stream: X split + GEMM1
    {
        long tx = (long)N_NODES * (KP1 / 4);
        k_split_x<<<(unsigned)((tx + 255) / 256), 256>>>(x);
    }
    cudaStreamWaitEvent(0, evW1, 0);
    dim3 gemm_grid(HDIM / BN, (N_NODES + BM - 1) / BM);
    k_gemm_bf3<<<gemm_grid, 256>>>(xh, xl, w1h, w1l, gh, N_NODES, KP1);

    // ---- join: agg needs g_dinv / g_off / g_csr; GEMM2 needs w2
    cudaStreamWaitEvent(0, evJoin, 0);
    k_agg<<<(N_NODES + 1) / 2, 128>>>(gh, b1, a1h, a1l);

    // layer 2
    k_gemm_bf3<<<gemm_grid, 256>>>(a1h, a1l, w2h, w2l, gh, N_NODES, HDIM);
    k_agg<<<(N_NODES + 1) / 2, 128>>>(gh, b2, a2h, a2l);

    // layer 3 (+ fused agg3/log_softmax tail)
    k_gemm3<<<(N_NODES + 7) / 8, 256>>>(a2h, a2l, W3);
    k_agg3_softmax<<<(N_NODES + 31) / 32, 256>>>(b3, out);
}